// round 11
// baseline (speedup 1.0000x reference)
#include <cuda_runtime.h>
#include <cuda_fp16.h>
#include <math.h>
#include <stdint.h>

#define N_INST 32768
#define D      2048
#define DP     512
#define CLASSES 4

#define TM 256            // instances per CTA
#define TN 128            // j per CTA
#define NSTAGE 4          // A-tile smem buffers (3 in flight)
#define STG 32768         // 32KB A per stage (B lives in registers from gmem)
#define NSTOT 32          // 32 k-tiles of 64

// ---------------- scratch (module-scope, no runtime allocation) ----------------
__device__ __align__(1024) uint8_t g_Vh[(size_t)N_INST * D * 2];   // fp16 V
__device__ __align__(1024) uint8_t g_Upk[DP * D * 2];              // fp16 U, fragment-packed
__device__ float g_Sp[4][N_INST];   // per-j-tile logit partials
__device__ float g_S[N_INST];
__device__ float g_bm[64], g_bz[64], g_MZ[2];
__device__ float g_tp[128][D];
__device__ float g_t[D];

// ---------------- PTX helpers (plain sm_80-era features only) ----------------
static __device__ __forceinline__ uint32_t smem_u32(const void* p) {
    uint32_t a;
    asm("{ .reg .u64 t; cvta.to.shared.u64 t, %1; cvt.u32.u64 %0, t; }" : "=r"(a) : "l"(p));
    return a;
}
static __device__ __forceinline__ void cp16(uint32_t dst, const void* src) {
    asm volatile("cp.async.cg.shared.global [%0], [%1], 16;" :: "r"(dst), "l"(src) : "memory");
}
static __device__ __forceinline__ void ldsm4(uint32_t* r, uint32_t addr) {
    asm volatile("ldmatrix.sync.aligned.m8n8.x4.shared.b16 {%0,%1,%2,%3}, [%4];"
                 : "=r"(r[0]), "=r"(r[1]), "=r"(r[2]), "=r"(r[3]) : "r"(addr));
}
static __device__ __forceinline__ void mma16816(float* d, const uint32_t* a, uint32_t b0, uint32_t b1) {
    asm volatile("mma.sync.aligned.m16n8k16.row.col.f32.f16.f16.f32 "
                 "{%0,%1,%2,%3}, {%4,%5,%6,%7}, {%8,%9}, {%0,%1,%2,%3};"
                 : "+f"(d[0]), "+f"(d[1]), "+f"(d[2]), "+f"(d[3])
                 : "r"(a[0]), "r"(a[1]), "r"(a[2]), "r"(a[3]), "r"(b0), "r"(b1));
}

// ---------------- pack kernels ----------------
__global__ __launch_bounds__(256) void k_packV(const float* __restrict__ V) {
    uint32_t idx = blockIdx.x * 256 + threadIdx.x;
    float4 v = ((const float4*)V)[idx];
    __half2 h01 = __floats2half2_rn(v.x, v.y);
    __half2 h23 = __floats2half2_rn(v.z, v.w);
    ((uint2*)g_Vh)[idx] = make_uint2(*(uint32_t*)&h01, *(uint32_t*)&h23);
}
// U -> canonical m16n8k16 B-fragment order:
// element t (uint2, 8B) = [jb(64)][kb(128)][lane(32)];
// lane l of block (jb,kb) holds U[jb*8 + l/4][kb*16 + (l&3)*2 .. +1] and [.. +8 .. +9].
__global__ __launch_bounds__(256) void k_packU(const float* __restrict__ U) {
    uint32_t t = blockIdx.x * 256 + threadIdx.x;     // 262,144
    uint32_t lane = t & 31;
    uint32_t kb   = (t >> 5) & 127;
    uint32_t jb   = t >> 12;
    const float* up = U + (size_t)(jb * 8 + (lane >> 2)) * D + kb * 16 + (lane & 3) * 2;
    __half2 lo = __floats2half2_rn(up[0], up[1]);
    __half2 hi = __floats2half2_rn(up[8], up[9]);
    ((uint2*)g_Upk)[t] = make_uint2(*(uint32_t*)&lo, *(uint32_t*)&hi);
}

// ---------------- main GEMM: A via smem/ldsm, B via gmem fragment LDG.64 ----------------
// smem per stage: A[256 rows x 128B] (32KB), xor-swizzled for conflict-free ldsm.
#define SMEM_BYTES (NSTAGE * STG + 512 + 4096 + 1024)

__global__ __launch_bounds__(512, 1) void k_scores_tc(const float* __restrict__ Wm)
{
    extern __shared__ uint8_t dsm[];
    uint32_t raw = smem_u32(dsm);
    uint32_t sb  = (raw + 1023) & ~1023u;
    uint8_t* sp  = dsm + (sb - raw);
    float* Wsh   = (float*)(sp + NSTAGE * STG);
    float* part  = (float*)(sp + NSTAGE * STG + 512);   // [4][256]

    const int tid  = threadIdx.x;
    const int lane = tid & 31, wid = tid >> 5;
    const int wm = wid & 3, wn = wid >> 2;          // warp tile: rows wm*64, cols wn*32
    const int ibase = blockIdx.x * TM;
    const int jbase = blockIdx.y * TN;

    if (tid < TN) Wsh[tid] = Wm[jbase + tid];

    const uint8_t* aT = g_Vh + (size_t)ibase * (D * 2);
    const uint2*   Bg = (const uint2*)g_Upk;
    // element index base for this warp: jb = blockIdx.y*16 + wn*4 (+nt), q = k16 index
    const uint32_t bidx0 = (uint32_t)(blockIdx.y * 16 + wn * 4) * 4096 + lane;

    // cp.async loader constants (each thread: 4 A-chunks of 16B)
    const uint32_t lrow   = tid >> 3;                       // 0..63
    const uint32_t lc16   = (tid & 7) * 16;
    const uint32_t ld_dst = lc16 ^ ((lrow & 7) << 4);       // swizzled col part

    // ldmatrix constants (A only)
    const uint32_t mask  = (lane & 7) << 4;
    const uint32_t aRow  = (wm * 64 + (lane & 15)) * 128;
    const uint32_t kselA = (lane & 16);        // k-half select for A x4

    float acc[4][4][4];
    #pragma unroll
    for (int a = 0; a < 4; ++a)
        #pragma unroll
        for (int b = 0; b < 4; ++b)
            #pragma unroll
            for (int c = 0; c < 4; ++c) acc[a][b][c] = 0.f;

    auto load_stage = [&](int s) {
        const int buf = s & (NSTAGE - 1);
        const uint8_t* as = aT + (size_t)s * 128;
        const uint32_t dA = sb + buf * STG;
        #pragma unroll
        for (int q = 0; q < 4; ++q) {
            uint32_t row = lrow + q * 64;
            cp16(dA + row * 128 + ld_dst, as + (size_t)row * 4096 + lc16);
        }
        asm volatile("cp.async.commit_group;" ::: "memory");
    };

    load_stage(0); load_stage(1); load_stage(2);

    // B fragment prefetch registers (q = flat k16 index 0..127)
    uint2 Bc[4], Bn[4];
    #pragma unroll
    for (int nt = 0; nt < 4; ++nt) Bc[nt] = __ldg(&Bg[bidx0 + nt * 4096]);

    #pragma unroll 1
    for (int s = 0; s < NSTOT; ++s) {
        asm volatile("cp.async.wait_group 2;" ::: "memory");
        __syncthreads();
        const int buf = s & (NSTAGE - 1);
        const uint32_t smA = sb + buf * STG;

        #pragma unroll
        for (int kk = 0; kk < 4; ++kk) {
            // prefetch next k16's B fragments (crosses stage boundary safely: gmem only)
            const int qn = (s * 4 + kk + 1 < 128) ? (s * 4 + kk + 1) : 127;
            #pragma unroll
            for (int nt = 0; nt < 4; ++nt)
                Bn[nt] = __ldg(&Bg[bidx0 + nt * 4096 + qn * 32]);

            const uint32_t kxA = (kk * 32 + kselA) ^ mask;
            uint32_t Af[4][4];
            #pragma unroll
            for (int mt = 0; mt < 4; ++mt) ldsm4(Af[mt], smA + aRow + mt * 2048 + kxA);
            #pragma unroll
            for (int mt = 0; mt < 4; ++mt)
                #pragma unroll
                for (int nt = 0; nt < 4; ++nt)
                    mma16816(acc[mt][nt], Af[mt], Bc[nt].x, Bc[nt].y);
            #pragma unroll
            for (int nt = 0; nt < 4; ++nt) Bc[nt] = Bn[nt];
        }
        if (s + 3 < NSTOT) load_stage(s + 3);
    }

    // ---- epilogue: s_part[i] = sum_{j in tile} w_j * tanh(c_ij) ----
    const int gr = lane >> 2;
    const int gc = (lane & 3) * 2;
    #pragma unroll
    for (int mt = 0; mt < 4; ++mt) {
        float l0 = 0.f, l1 = 0.f;
        #pragma unroll
        for (int nt = 0; nt < 4; ++nt) {
            int wi = wn * 32 + nt * 8 + gc;
            float w0 = Wsh[wi], w1 = Wsh[wi + 1];
            l0 += w0 * tanhf(acc[mt][nt][0]) + w1 * tanhf(acc[mt][nt][1]);
            l1 += w0 * tanhf(acc[mt][nt][2]) + w1 * tanhf(acc[mt][nt][3]);
        }
        l0 += __shfl_xor_sync(0xffffffffu, l0, 1);
        l0 += __shfl_xor_sync(0xffffffffu, l0, 2);
        l1 += __shfl_xor_sync(0xffffffffu, l1, 1);
        l1 += __shfl_xor_sync(0xffffffffu, l1, 2);
        if ((lane & 3) == 0) {
            part[wn * 256 + wm * 64 + mt * 16 + gr]     = l0;
            part[wn * 256 + wm * 64 + mt * 16 + 8 + gr] = l1;
        }
    }
    __syncthreads();
    if (tid < 256) {
        float sv = part[tid] + part[256 + tid] + part[512 + tid] + part[768 + tid];
        g_Sp[blockIdx.y][ibase + tid] = sv;
    }
}

// ---------------- parallel softmax stats (2 tiny kernels) ----------------
__global__ __launch_bounds__(512) void k_smax1() {
    __shared__ float sm[512];
    const int tid = threadIdx.x;
    const int i = blockIdx.x * 512 + tid;
    float s = g_Sp[0][i] + g_Sp[1][i] + g_Sp[2][i] + g_Sp[3][i];
    g_S[i] = s;
    sm[tid] = s; __syncthreads();
    for (int o = 256; o > 0; o >>= 1) {
        if (tid < o) sm[tid] = fmaxf(sm[tid], sm[tid + o]);
        __syncthreads();
    }
    const float bm = sm[0];
    __syncthreads();
    sm[tid] = expf(s - bm); __syncthreads();
    for (int o = 256; o > 0; o >>= 1) {
        if (tid < o) sm[tid] += sm[tid + o];
        __syncthreads();
    }
    if (tid == 0) { g_bm[blockIdx.x] = bm; g_bz[blockIdx.x] = sm[0]; }
}
__global__ void k_smax2() {
    __shared__ float m[64], z[64];
    const int tid = threadIdx.x;   // 64
    m[tid] = g_bm[tid]; z[tid] = g_bz[tid];
    __syncthreads();
    for (int o = 32; o > 0; o >>= 1) {
        if (tid < o) m[tid] = fmaxf(m[tid], m[tid + o]);
        __syncthreads();
    }
    const float M = m[0];
    __syncthreads();
    z[tid] *= expf(g_bm[tid] - M);
    __syncthreads();
    for (int o = 32; o > 0; o >>= 1) {
        if (tid < o) z[tid] += z[tid + o];
        __syncthreads();
    }
    if (tid == 0) { g_MZ[0] = M; g_MZ[1] = 1.0f / z[0]; }
}

// ---------------- pooling: fp16 V, high-MLP, fused normalize ----------------
// grid (2,128): x = 1024-col half, y = 256-row stripe. 256 threads, 4 cols each.
__global__ __launch_bounds__(256) void k_pool() {
    __shared__ float ash[256];
    const int tid = threadIdx.x;
    const int c   = blockIdx.x * 1024 + tid * 4;
    const int i0  = blockIdx.y * 256;
    const float M = g_MZ[0], invZ = g_MZ[1];

    ash[tid] = expf(g_S[i0 + tid] - M) * invZ;
    __syncthreads();

    float4 acc = make_float4(0.f, 0.f, 0.f, 0.f);
    const uint2* vp = (const uint2*)(g_Vh + ((size_t)i0 * D + c) * 2);
    #pragma unroll 8
    for (int i = 0; i < 256; ++i) {
        float a = ash[i];
        uint2 r = vp[(size_t)i * (D / 4)];
        float2 f0 = __half22float2(*(const __half2*)&r.x);
        float2 f1 = __half22float2(*(const __half2*)&r.y);
        acc.x += a * f0.x; acc.y += a * f0.y;
        acc.z += a * f1.x; acc.w += a * f1.y;
    }
    *(float4*)&g_tp[blockIdx.y][c] = acc;
}
__global__ void k_pool_reduce() {
    const int k = blockIdx.x * blockDim.x + threadIdx.x;
    float s = 0.f;
    #pragma unroll
    for (int r = 0; r < 128; ++r) s += g_tp[r][k];
    g_t[k] = s;
}

// ---------------- final linear ----------------
__global__ void k_final(const float* __restrict__ W, float* __restrict__ out) {
    const int c    = threadIdx.y;
    const int lane = threadIdx.x;
    float s = 0.f;
    for (int k = lane; k < D; k += 32) s += W[c * D + k] * g_t[k];
    #pragma unroll
    for (int o = 16; o > 0; o >>= 1) s += __shfl_down_sync(0xffffffff, s, o);
    if (lane == 0) out[c] = s;
}

// ---------------- launcher (single stream; fork measured neutral in R10) ----------------
extern "C" void kernel_launch(void* const* d_in, const int* in_sizes, int n_in,
                              void* d_out, int out_size)
{
    const float* V  = (const float*)d_in[0];   // V_prime [32768, 2048]
    const float* U  = (const float*)d_in[1];   // U_t     [512, 2048]
    const float* Wm = (const float*)d_in[2];   // W_mta   [1, 512]
    const float* W  = (const float*)d_in[3];   // W       [4, 2048]
    float* out = (float*)d_out;

    cudaFuncSetAttribute(k_scores_tc, cudaFuncAttributeMaxDynamicSharedMemorySize, SMEM_BYTES);

    k_packU<<<1024, 256>>>(U);
    k_packV<<<65536, 256>>>(V);
    k_scores_tc<<<dim3(128, 4), 512, SMEM_BYTES>>>(Wm);
    k_smax1<<<64, 512>>>();
    k_smax2<<<1, 64>>>();
    k_pool<<<dim3(2, 128), 256>>>();
    k_pool_reduce<<<2, 1024>>>();
    k_final<<<1, dim3(32, 4)>>>(W, out);
}

// round 12
// speedup vs baseline: 1.1500x; 1.1500x over previous
#include <cuda_runtime.h>
#include <cuda_fp16.h>
#include <math.h>
#include <stdint.h>

#define N_INST 32768
#define D      2048
#define DP     512
#define CLASSES 4

#define TM 256            // instances per CTA
#define TN 128            // j per CTA
#define NSTAGE 4          // smem buffers (3 in flight)
#define STG 49152         // 32KB A + 16KB B per stage
#define NSTOT 32          // 32 k-tiles of 64

// ---------------- scratch (module-scope, no runtime allocation) ----------------
__device__ __align__(1024) uint8_t g_Vh[(size_t)N_INST * D * 2];   // fp16 V
__device__ __align__(1024) uint8_t g_Uh[DP * D * 2];               // fp16 U
__device__ float g_Sp[4][N_INST];   // per-j-tile logit partials
__device__ float g_S[N_INST];
__device__ float g_bm[64], g_bz[64], g_MZ[2];
__device__ float g_tp[128][D];
__device__ float g_t[D];

// ---------------- PTX helpers (plain sm_80-era features only) ----------------
static __device__ __forceinline__ uint32_t smem_u32(const void* p) {
    uint32_t a;
    asm("{ .reg .u64 t; cvta.to.shared.u64 t, %1; cvt.u32.u64 %0, t; }" : "=r"(a) : "l"(p));
    return a;
}
static __device__ __forceinline__ void cp16(uint32_t dst, const void* src) {
    asm volatile("cp.async.cg.shared.global [%0], [%1], 16;" :: "r"(dst), "l"(src) : "memory");
}
static __device__ __forceinline__ void ldsm4(uint32_t* r, uint32_t addr) {
    asm volatile("ldmatrix.sync.aligned.m8n8.x4.shared.b16 {%0,%1,%2,%3}, [%4];"
                 : "=r"(r[0]), "=r"(r[1]), "=r"(r[2]), "=r"(r[3]) : "r"(addr));
}
static __device__ __forceinline__ void mma16816(float* d, const uint32_t* a, uint32_t b0, uint32_t b1) {
    asm volatile("mma.sync.aligned.m16n8k16.row.col.f32.f16.f16.f32 "
                 "{%0,%1,%2,%3}, {%4,%5,%6,%7}, {%8,%9}, {%0,%1,%2,%3};"
                 : "+f"(d[0]), "+f"(d[1]), "+f"(d[2]), "+f"(d[3])
                 : "r"(a[0]), "r"(a[1]), "r"(a[2]), "r"(a[3]), "r"(b0), "r"(b1));
}

// ---------------- pack: fp32 -> fp16, grid-stride fat kernels ----------------
// V: 16,777,216 quads; 1024 CTAs x 256 thr x 64 iters (unroll 4 for MLP).
__global__ __launch_bounds__(256) void k_packV(const float* __restrict__ V) {
    const uint32_t stride = 1024 * 256;
    uint32_t idx = blockIdx.x * 256 + threadIdx.x;
    #pragma unroll 4
    for (int it = 0; it < 64; ++it, idx += stride) {
        float4 v = ((const float4*)V)[idx];
        __half2 h01 = __floats2half2_rn(v.x, v.y);
        __half2 h23 = __floats2half2_rn(v.z, v.w);
        ((uint2*)g_Vh)[idx] = make_uint2(*(uint32_t*)&h01, *(uint32_t*)&h23);
    }
}
// U: 262,144 quads; 128 CTAs x 256 thr x 8 iters.
__global__ __launch_bounds__(256) void k_packU(const float* __restrict__ U) {
    const uint32_t stride = 128 * 256;
    uint32_t idx = blockIdx.x * 256 + threadIdx.x;
    #pragma unroll 4
    for (int it = 0; it < 8; ++it, idx += stride) {
        float4 v = ((const float4*)U)[idx];
        __half2 h01 = __floats2half2_rn(v.x, v.y);
        __half2 h23 = __floats2half2_rn(v.z, v.w);
        ((uint2*)g_Uh)[idx] = make_uint2(*(uint32_t*)&h01, *(uint32_t*)&h23);
    }
}

// ---------------- main GEMM: EXACT R9 config (measured ~190us total) ----------------
// C[256x128] tile, 512 threads, grid (128,4) i-fastest.
// smem per stage: A[256 rows x 128B] (32KB) + B[128 rows x 128B] (16KB),
// xor-swizzled (bits[6:4] ^= row%8) for conflict-free ldmatrix.
#define SMEM_BYTES (NSTAGE * STG + 512 + 4096 + 1024)

__global__ __launch_bounds__(512, 1) void k_scores_tc(const float* __restrict__ Wm)
{
    extern __shared__ uint8_t dsm[];
    uint32_t raw = smem_u32(dsm);
    uint32_t sb  = (raw + 1023) & ~1023u;
    uint8_t* sp  = dsm + (sb - raw);
    float* Wsh   = (float*)(sp + NSTAGE * STG);
    float* part  = (float*)(sp + NSTAGE * STG + 512);   // [4][256]

    const int tid  = threadIdx.x;
    const int lane = tid & 31, wid = tid >> 5;
    const int wm = wid & 3, wn = wid >> 2;          // warp tile: rows wm*64, cols wn*32
    const int ibase = blockIdx.x * TM;
    const int jbase = blockIdx.y * TN;

    if (tid < TN) Wsh[tid] = Wm[jbase + tid];

    const uint8_t* aT = g_Vh + (size_t)ibase * (D * 2);
    const uint8_t* bT = g_Uh + (size_t)jbase * (D * 2);

    // cp.async loader constants (each thread: 4 A-chunks + 2 B-chunks of 16B)
    const uint32_t lrow   = tid >> 3;                       // 0..63
    const uint32_t lc16   = (tid & 7) * 16;
    const uint32_t ld_dst = lc16 ^ ((lrow & 7) << 4);       // swizzled col part

    // ldmatrix constants
    const uint32_t mask  = (lane & 7) << 4;
    const uint32_t aRow  = (wm * 64 + (lane & 15)) * 128;
    const uint32_t bRow  = (wn * 32 + (lane & 7) + ((lane >> 1) & 8)) * 128;
    const uint32_t kselA = (lane & 16);        // k-half select for A x4
    const uint32_t kselB = (lane & 8) << 1;    // k-half select for B x4

    float acc[4][4][4];
    #pragma unroll
    for (int a = 0; a < 4; ++a)
        #pragma unroll
        for (int b = 0; b < 4; ++b)
            #pragma unroll
            for (int c = 0; c < 4; ++c) acc[a][b][c] = 0.f;

    auto load_stage = [&](int s) {
        const int buf = s & (NSTAGE - 1);
        const uint8_t* as = aT + (size_t)s * 128;
        const uint8_t* bs = bT + (size_t)s * 128;
        const uint32_t dA = sb + buf * STG;
        const uint32_t dB = dA + 32768;
        #pragma unroll
        for (int q = 0; q < 4; ++q) {
            uint32_t row = lrow + q * 64;
            cp16(dA + row * 128 + ld_dst, as + (size_t)row * 4096 + lc16);
        }
        #pragma unroll
        for (int q = 0; q < 2; ++q) {
            uint32_t row = lrow + q * 64;
            cp16(dB + row * 128 + ld_dst, bs + (size_t)row * 4096 + lc16);
        }
        asm volatile("cp.async.commit_group;" ::: "memory");
    };

    load_stage(0); load_stage(1); load_stage(2);

    #pragma unroll 1
    for (int s = 0; s < NSTOT; ++s) {
        asm volatile("cp.async.wait_group 2;" ::: "memory");
        __syncthreads();
        const int buf = s & (NSTAGE - 1);
        const uint32_t smA = sb + buf * STG;
        const uint32_t smB = smA + 32768;

        #pragma unroll
        for (int kk = 0; kk < 4; ++kk) {
            const uint32_t kxA = (kk * 32 + kselA) ^ mask;
            const uint32_t kxB = (kk * 32 + kselB) ^ mask;
            uint32_t Af[4][4], Bf[2][4];
            #pragma unroll
            for (int mt = 0; mt < 4; ++mt) ldsm4(Af[mt], smA + aRow + mt * 2048 + kxA);
            #pragma unroll
            for (int p = 0; p < 2; ++p)   ldsm4(Bf[p],  smB + bRow + p  * 2048 + kxB);
            #pragma unroll
            for (int mt = 0; mt < 4; ++mt)
                #pragma unroll
                for (int nt = 0; nt < 4; ++nt) {
                    const uint32_t* B = Bf[nt >> 1];
                    mma16816(acc[mt][nt], Af[mt],
                             (nt & 1) ? B[2] : B[0], (nt & 1) ? B[3] : B[1]);
                }
        }
        if (s + 3 < NSTOT) load_stage(s + 3);
    }

    // ---- epilogue: s_part[i] = sum_{j in tile} w_j * tanh(c_ij) ----
    const int gr = lane >> 2;
    const int gc = (lane & 3) * 2;
    #pragma unroll
    for (int mt = 0; mt < 4; ++mt) {
        float l0 = 0.f, l1 = 0.f;
        #pragma unroll
        for (int nt = 0; nt < 4; ++nt) {
            int wi = wn * 32 + nt * 8 + gc;
            float w0 = Wsh[wi], w1 = Wsh[wi + 1];
            l0 += w0 * tanhf(acc[mt][nt][0]) + w1 * tanhf(acc[mt][nt][1]);
            l1 += w0 * tanhf(acc[mt][nt][2]) + w1 * tanhf(acc[mt][nt][3]);
        }
        l0 += __shfl_xor_sync(0xffffffffu, l0, 1);
        l0 += __shfl_xor_sync(0xffffffffu, l0, 2);
        l1 += __shfl_xor_sync(0xffffffffu, l1, 1);
        l1 += __shfl_xor_sync(0xffffffffu, l1, 2);
        if ((lane & 3) == 0) {
            part[wn * 256 + wm * 64 + mt * 16 + gr]     = l0;
            part[wn * 256 + wm * 64 + mt * 16 + 8 + gr] = l1;
        }
    }
    __syncthreads();
    if (tid < 256) {
        float sv = part[tid] + part[256 + tid] + part[512 + tid] + part[768 + tid];
        g_Sp[blockIdx.y][ibase + tid] = sv;
    }
}

// ---------------- parallel softmax stats (2 tiny kernels) ----------------
__global__ __launch_bounds__(512) void k_smax1() {
    __shared__ float sm[512];
    const int tid = threadIdx.x;
    const int i = blockIdx.x * 512 + tid;
    float s = g_Sp[0][i] + g_Sp[1][i] + g_Sp[2][i] + g_Sp[3][i];
    g_S[i] = s;
    sm[tid] = s; __syncthreads();
    for (int o = 256; o > 0; o >>= 1) {
        if (tid < o) sm[tid] = fmaxf(sm[tid], sm[tid + o]);
        __syncthreads();
    }
    const float bm = sm[0];
    __syncthreads();
    sm[tid] = expf(s - bm); __syncthreads();
    for (int o = 256; o > 0; o >>= 1) {
        if (tid < o) sm[tid] += sm[tid + o];
        __syncthreads();
    }
    if (tid == 0) { g_bm[blockIdx.x] = bm; g_bz[blockIdx.x] = sm[0]; }
}
__global__ void k_smax2() {
    __shared__ float m[64], z[64];
    const int tid = threadIdx.x;   // 64
    m[tid] = g_bm[tid]; z[tid] = g_bz[tid];
    __syncthreads();
    for (int o = 32; o > 0; o >>= 1) {
        if (tid < o) m[tid] = fmaxf(m[tid], m[tid + o]);
        __syncthreads();
    }
    const float M = m[0];
    __syncthreads();
    z[tid] *= expf(g_bm[tid] - M);
    __syncthreads();
    for (int o = 32; o > 0; o >>= 1) {
        if (tid < o) z[tid] += z[tid + o];
        __syncthreads();
    }
    if (tid == 0) { g_MZ[0] = M; g_MZ[1] = 1.0f / z[0]; }
}

// ---------------- pooling: fp16 V, high-MLP, fused normalize ----------------
// grid (2,128): x = 1024-col half, y = 256-row stripe. 256 threads, 4 cols each.
__global__ __launch_bounds__(256) void k_pool() {
    __shared__ float ash[256];
    const int tid = threadIdx.x;
    const int c   = blockIdx.x * 1024 + tid * 4;
    const int i0  = blockIdx.y * 256;
    const float M = g_MZ[0], invZ = g_MZ[1];

    ash[tid] = expf(g_S[i0 + tid] - M) * invZ;
    __syncthreads();

    float4 acc = make_float4(0.f, 0.f, 0.f, 0.f);
    const uint2* vp = (const uint2*)(g_Vh + ((size_t)i0 * D + c) * 2);
    #pragma unroll 8
    for (int i = 0; i < 256; ++i) {
        float a = ash[i];
        uint2 r = vp[(size_t)i * (D / 4)];
        float2 f0 = __half22float2(*(const __half2*)&r.x);
        float2 f1 = __half22float2(*(const __half2*)&r.y);
        acc.x += a * f0.x; acc.y += a * f0.y;
        acc.z += a * f1.x; acc.w += a * f1.y;
    }
    *(float4*)&g_tp[blockIdx.y][c] = acc;
}
__global__ void k_pool_reduce() {
    const int k = blockIdx.x * blockDim.x + threadIdx.x;
    float s = 0.f;
    #pragma unroll
    for (int r = 0; r < 128; ++r) s += g_tp[r][k];
    g_t[k] = s;
}

// ---------------- final linear ----------------
__global__ void k_final(const float* __restrict__ W, float* __restrict__ out) {
    const int c    = threadIdx.y;
    const int lane = threadIdx.x;
    float s = 0.f;
    for (int k = lane; k < D; k += 32) s += W[c * D + k] * g_t[k];
    #pragma unroll
    for (int o = 16; o > 0; o >>= 1) s += __shfl_down_sync(0xffffffff, s, o);
    if (lane == 0) out[c] = s;
}

// ---------------- launcher ----------------
extern "C" void kernel_launch(void* const* d_in, const int* in_sizes, int n_in,
                              void* d_out, int out_size)
{
    const float* V  = (const float*)d_in[0];   // V_prime [32768, 2048]
    const float* U  = (const float*)d_in[1];   // U_t     [512, 2048]
    const float* Wm = (const float*)d_in[2];   // W_mta   [1, 512]
    const float* W  = (const float*)d_in[3];   // W       [4, 2048]
    float* out = (float*)d_out;

    cudaFuncSetAttribute(k_scores_tc, cudaFuncAttributeMaxDynamicSharedMemorySize, SMEM_BYTES);

    k_packU<<<128, 256>>>(U);
    k_packV<<<1024, 256>>>(V);
    k_scores_tc<<<dim3(128, 4), 512, SMEM_BYTES>>>(Wm);
    k_smax1<<<64, 512>>>();
    k_smax2<<<1, 64>>>();
    k_pool<<<dim3(2, 128), 256>>>();
    k_pool_reduce<<<2, 1024>>>();
    k_final<<<1, dim3(32, 4)>>>(W, out);
}

// round 13
// speedup vs baseline: 1.1563x; 1.0055x over previous
#include <cuda_runtime.h>
#include <cuda_fp16.h>
#include <math.h>
#include <stdint.h>

#define N_INST 32768
#define D      2048
#define DP     512
#define CLASSES 4

#define TM 256            // instances per CTA
#define TN 128            // j per CTA
#define NSTAGE 4          // smem buffers (3 in flight)
#define STG 49152         // 32KB A + 16KB B per stage
#define NSTOT 32          // 32 k-tiles of 64

// ---------------- scratch (module-scope, no runtime allocation) ----------------
__device__ __align__(1024) uint8_t g_Vh[(size_t)N_INST * D * 2];   // fp16 V
__device__ __align__(1024) uint8_t g_Uh[DP * D * 2];               // fp16 U
__device__ float g_Sp[4][N_INST];   // per-j-tile logit partials
__device__ float g_S[N_INST];
__device__ float g_bm[64], g_bz[64], g_MZ[2];
__device__ float g_tp[128][D];
__device__ float g_t[D];

// ---------------- PTX helpers (plain sm_80-era features only) ----------------
static __device__ __forceinline__ uint32_t smem_u32(const void* p) {
    uint32_t a;
    asm("{ .reg .u64 t; cvta.to.shared.u64 t, %1; cvt.u32.u64 %0, t; }" : "=r"(a) : "l"(p));
    return a;
}
static __device__ __forceinline__ void cp16(uint32_t dst, const void* src) {
    asm volatile("cp.async.cg.shared.global [%0], [%1], 16;" :: "r"(dst), "l"(src) : "memory");
}
static __device__ __forceinline__ void ldsm4(uint32_t* r, uint32_t addr) {
    asm volatile("ldmatrix.sync.aligned.m8n8.x4.shared.b16 {%0,%1,%2,%3}, [%4];"
                 : "=r"(r[0]), "=r"(r[1]), "=r"(r[2]), "=r"(r[3]) : "r"(addr));
}
static __device__ __forceinline__ void mma16816(float* d, const uint32_t* a, uint32_t b0, uint32_t b1) {
    asm volatile("mma.sync.aligned.m16n8k16.row.col.f32.f16.f16.f32 "
                 "{%0,%1,%2,%3}, {%4,%5,%6,%7}, {%8,%9}, {%0,%1,%2,%3};"
                 : "+f"(d[0]), "+f"(d[1]), "+f"(d[2]), "+f"(d[3])
                 : "r"(a[0]), "r"(a[1]), "r"(a[2]), "r"(a[3]), "r"(b0), "r"(b1));
}

// ---------------- pack: fp32 -> fp16, grid-stride fat kernels ----------------
__global__ __launch_bounds__(256) void k_packV(const float* __restrict__ V) {
    const uint32_t stride = 1024 * 256;
    uint32_t idx = blockIdx.x * 256 + threadIdx.x;
    #pragma unroll 4
    for (int it = 0; it < 64; ++it, idx += stride) {
        float4 v = ((const float4*)V)[idx];
        __half2 h01 = __floats2half2_rn(v.x, v.y);
        __half2 h23 = __floats2half2_rn(v.z, v.w);
        ((uint2*)g_Vh)[idx] = make_uint2(*(uint32_t*)&h01, *(uint32_t*)&h23);
    }
}
__global__ __launch_bounds__(256) void k_packU(const float* __restrict__ U) {
    const uint32_t stride = 128 * 256;
    uint32_t idx = blockIdx.x * 256 + threadIdx.x;
    #pragma unroll 4
    for (int it = 0; it < 8; ++it, idx += stride) {
        float4 v = ((const float4*)U)[idx];
        __half2 h01 = __floats2half2_rn(v.x, v.y);
        __half2 h23 = __floats2half2_rn(v.z, v.w);
        ((uint2*)g_Uh)[idx] = make_uint2(*(uint32_t*)&h01, *(uint32_t*)&h23);
    }
}

// ---------------- main GEMM: C[256x128] tile, 256 thr / 8 warps of 64x64 ----------------
// Same stage layout as R6/R9/R12: A[256x128B]=32KB + B[128x128B]=16KB per stage,
// xor-swizzled (bits[6:4] ^= row%8). Warp tile 64x64: 8 ldsm -> 32 HMMA per kk.
#define SMEM_BYTES (NSTAGE * STG + 512 + 4096 + 1024)

__global__ __launch_bounds__(256, 1) void k_scores_tc(const float* __restrict__ Wm)
{
    extern __shared__ uint8_t dsm[];
    uint32_t raw = smem_u32(dsm);
    uint32_t sb  = (raw + 1023) & ~1023u;
    uint8_t* sp  = dsm + (sb - raw);
    float* Wsh   = (float*)(sp + NSTAGE * STG);
    float* part  = (float*)(sp + NSTAGE * STG + 512);   // [2][256]

    const int tid  = threadIdx.x;
    const int lane = tid & 31, wid = tid >> 5;          // 8 warps
    const int wm = wid & 3, wn = wid >> 2;              // warp tile: rows wm*64, cols wn*64
    const int ibase = blockIdx.x * TM;
    const int jbase = blockIdx.y * TN;

    if (tid < TN) Wsh[tid] = Wm[jbase + tid];

    const uint8_t* aT = g_Vh + (size_t)ibase * (D * 2);
    const uint8_t* bT = g_Uh + (size_t)jbase * (D * 2);

    // cp.async loader: 256 threads; A 8 chunks + B 4 chunks of 16B each
    const uint32_t lrow   = tid >> 3;                       // 0..31
    const uint32_t lc16   = (tid & 7) * 16;
    const uint32_t ld_dst = lc16 ^ ((lrow & 7) << 4);       // swizzled col part

    // ldmatrix constants
    const uint32_t mask  = (lane & 7) << 4;
    const uint32_t aRow  = (wm * 64 + (lane & 15)) * 128;
    const uint32_t bRow  = (wn * 64 + (lane & 7) + ((lane >> 1) & 8)) * 128;
    const uint32_t kselA = (lane & 16);        // k-half select for A x4
    const uint32_t kselB = (lane & 8) << 1;    // k-half select for B x4

    float acc[4][8][4];
    #pragma unroll
    for (int a = 0; a < 4; ++a)
        #pragma unroll
        for (int b = 0; b < 8; ++b)
            #pragma unroll
            for (int c = 0; c < 4; ++c) acc[a][b][c] = 0.f;

    auto load_stage = [&](int s) {
        const int buf = s & (NSTAGE - 1);
        const uint8_t* as = aT + (size_t)s * 128;
        const uint8_t* bs = bT + (size_t)s * 128;
        const uint32_t dA = sb + buf * STG;
        const uint32_t dB = dA + 32768;
        #pragma unroll
        for (int q = 0; q < 8; ++q) {
            uint32_t row = lrow + q * 32;
            cp16(dA + row * 128 + ld_dst, as + (size_t)row * 4096 + lc16);
        }
        #pragma unroll
        for (int q = 0; q < 4; ++q) {
            uint32_t row = lrow + q * 32;
            cp16(dB + row * 128 + ld_dst, bs + (size_t)row * 4096 + lc16);
        }
        asm volatile("cp.async.commit_group;" ::: "memory");
    };

    load_stage(0); load_stage(1); load_stage(2);

    #pragma unroll 1
    for (int s = 0; s < NSTOT; ++s) {
        asm volatile("cp.async.wait_group 2;" ::: "memory");
        __syncthreads();
        const int buf = s & (NSTAGE - 1);
        const uint32_t smA = sb + buf * STG;
        const uint32_t smB = smA + 32768;

        #pragma unroll
        for (int kk = 0; kk < 4; ++kk) {
            const uint32_t kxA = (kk * 32 + kselA) ^ mask;
            const uint32_t kxB = (kk * 32 + kselB) ^ mask;
            uint32_t Af[4][4], Bf[4][4];
            #pragma unroll
            for (int mt = 0; mt < 4; ++mt) ldsm4(Af[mt], smA + aRow + mt * 2048 + kxA);
            #pragma unroll
            for (int p = 0; p < 4; ++p)   ldsm4(Bf[p],  smB + bRow + p  * 2048 + kxB);
            #pragma unroll
            for (int mt = 0; mt < 4; ++mt)
                #pragma unroll
                for (int nt = 0; nt < 8; ++nt) {
                    const uint32_t* B = Bf[nt >> 1];
                    mma16816(acc[mt][nt], Af[mt],
                             (nt & 1) ? B[2] : B[0], (nt & 1) ? B[3] : B[1]);
                }
        }
        if (s + 3 < NSTOT) load_stage(s + 3);
    }

    // ---- epilogue: s_part[i] = sum_{j in tile} w_j * tanh(c_ij) ----
    const int gr = lane >> 2;
    const int gc = (lane & 3) * 2;
    #pragma unroll
    for (int mt = 0; mt < 4; ++mt) {
        float l0 = 0.f, l1 = 0.f;
        #pragma unroll
        for (int nt = 0; nt < 8; ++nt) {
            int wi = wn * 64 + nt * 8 + gc;
            float w0 = Wsh[wi], w1 = Wsh[wi + 1];
            l0 += w0 * tanhf(acc[mt][nt][0]) + w1 * tanhf(acc[mt][nt][1]);
            l1 += w0 * tanhf(acc[mt][nt][2]) + w1 * tanhf(acc[mt][nt][3]);
        }
        l0 += __shfl_xor_sync(0xffffffffu, l0, 1);
        l0 += __shfl_xor_sync(0xffffffffu, l0, 2);
        l1 += __shfl_xor_sync(0xffffffffu, l1, 1);
        l1 += __shfl_xor_sync(0xffffffffu, l1, 2);
        if ((lane & 3) == 0) {
            part[wn * 256 + wm * 64 + mt * 16 + gr]     = l0;
            part[wn * 256 + wm * 64 + mt * 16 + 8 + gr] = l1;
        }
    }
    __syncthreads();
    if (tid < 256) {
        float sv = part[tid] + part[256 + tid];
        g_Sp[blockIdx.y][ibase + tid] = sv;
    }
}

// ---------------- parallel softmax stats (2 tiny kernels) ----------------
__global__ __launch_bounds__(512) void k_smax1() {
    __shared__ float sm[512];
    const int tid = threadIdx.x;
    const int i = blockIdx.x * 512 + tid;
    float s = g_Sp[0][i] + g_Sp[1][i] + g_Sp[2][i] + g_Sp[3][i];
    g_S[i] = s;
    sm[tid] = s; __syncthreads();
    for (int o = 256; o > 0; o >>= 1) {
        if (tid < o) sm[tid] = fmaxf(sm[tid], sm[tid + o]);
        __syncthreads();
    }
    const float bm = sm[0];
    __syncthreads();
    sm[tid] = expf(s - bm); __syncthreads();
    for (int o = 256; o > 0; o >>= 1) {
        if (tid < o) sm[tid] += sm[tid + o];
        __syncthreads();
    }
    if (tid == 0) { g_bm[blockIdx.x] = bm; g_bz[blockIdx.x] = sm[0]; }
}
__global__ void k_smax2() {
    __shared__ float m[64], z[64];
    const int tid = threadIdx.x;   // 64
    m[tid] = g_bm[tid]; z[tid] = g_bz[tid];
    __syncthreads();
    for (int o = 32; o > 0; o >>= 1) {
        if (tid < o) m[tid] = fmaxf(m[tid], m[tid + o]);
        __syncthreads();
    }
    const float M = m[0];
    __syncthreads();
    z[tid] *= expf(g_bm[tid] - M);
    __syncthreads();
    for (int o = 32; o > 0; o >>= 1) {
        if (tid < o) z[tid] += z[tid + o];
        __syncthreads();
    }
    if (tid == 0) { g_MZ[0] = M; g_MZ[1] = 1.0f / z[0]; }
}

// ---------------- pooling: fp16 V, high-MLP, fused normalize ----------------
__global__ __launch_bounds__(256) void k_pool() {
    __shared__ float ash[256];
    const int tid = threadIdx.x;
    const int c   = blockIdx.x * 1024 + tid * 4;
    const int i0  = blockIdx.y * 256;
    const float M = g_MZ[0], invZ = g_MZ[1];

    ash[tid] = expf(g_S[i0 + tid] - M) * invZ;
    __syncthreads();

    float4 acc = make_float4(0.f, 0.f, 0.f, 0.f);
    const uint2* vp = (const uint2*)(g_Vh + ((size_t)i0 * D + c) * 2);
    #pragma unroll 8
    for (int i = 0; i < 256; ++i) {
        float a = ash[i];
        uint2 r = vp[(size_t)i * (D / 4)];
        float2 f0 = __half22float2(*(const __half2*)&r.x);
        float2 f1 = __half22float2(*(const __half2*)&r.y);
        acc.x += a * f0.x; acc.y += a * f0.y;
        acc.z += a * f1.x; acc.w += a * f1.y;
    }
    *(float4*)&g_tp[blockIdx.y][c] = acc;
}
__global__ void k_pool_reduce() {
    const int k = blockIdx.x * blockDim.x + threadIdx.x;
    float s = 0.f;
    #pragma unroll
    for (int r = 0; r < 128; ++r) s += g_tp[r][k];
    g_t[k] = s;
}

// ---------------- final linear ----------------
__global__ void k_final(const float* __restrict__ W, float* __restrict__ out) {
    const int c    = threadIdx.y;
    const int lane = threadIdx.x;
    float s = 0.f;
    for (int k = lane; k < D; k += 32) s += W[c * D + k] * g_t[k];
    #pragma unroll
    for (int o = 16; o > 0; o >>= 1) s += __shfl_down_sync(0xffffffff, s, o);
    if (lane == 0) out[c] = s;
}

// ---------------- launcher ----------------
extern "C" void kernel_launch(void* const* d_in, const int* in_sizes, int n_in,
                              void* d_out, int out_size)
{
    const float* V  = (const float*)d_in[0];   // V_prime [32768, 2048]
    const float* U  = (const float*)d_in[1];   // U_t     [512, 2048]
    const float* Wm = (const float*)d_in[2];   // W_mta   [1, 512]
    const float* W  = (const float*)d_in[3];   // W       [4, 2048]
    float* out = (float*)d_out;

    cudaFuncSetAttribute(k_scores_tc, cudaFuncAttributeMaxDynamicSharedMemorySize, SMEM_BYTES);

    k_packU<<<128, 256>>>(U);
    k_packV<<<1024, 256>>>(V);
    k_scores_tc<<<dim3(128, 4), 256, SMEM_BYTES>>>(Wm);
    k_smax1<<<64, 512>>>();
    k_smax2<<<1, 64>>>();
    k_pool<<<dim3(2, 128), 256>>>();
    k_pool_reduce<<<2, 1024>>>();
    k_final<<<1, dim3(32, 4)>>>(W, out);
}

// round 14
// speedup vs baseline: 1.1631x; 1.0059x over previous
#include <cuda_runtime.h>
#include <cuda_fp16.h>
#include <math.h>
#include <stdint.h>

#define N_INST 32768
#define D      2048
#define DP     512
#define CLASSES 4

#define TM 256            // instances per CTA
#define TN 128            // j per CTA
#define NSTAGE 4          // smem buffers (3 in flight)
#define STG 49152         // 32KB A + 16KB B per stage
#define NSTOT 32          // 32 k-tiles of 64

// ---------------- scratch (module-scope, no runtime allocation) ----------------
__device__ __align__(1024) uint8_t g_Vh[(size_t)N_INST * D * 2];   // fp16 V
__device__ __align__(1024) uint8_t g_Uh[DP * D * 2];               // fp16 U
__device__ float g_Sp[4][N_INST];   // per-j-tile logit partials
__device__ float g_S[N_INST];
__device__ float g_bm[64], g_bz[64], g_MZ[2];
__device__ float g_tp[128][D];
__device__ float g_t[D];

// ---------------- PTX helpers (plain sm_80-era features only) ----------------
static __device__ __forceinline__ uint32_t smem_u32(const void* p) {
    uint32_t a;
    asm("{ .reg .u64 t; cvta.to.shared.u64 t, %1; cvt.u32.u64 %0, t; }" : "=r"(a) : "l"(p));
    return a;
}
static __device__ __forceinline__ void cp16(uint32_t dst, const void* src) {
    asm volatile("cp.async.cg.shared.global [%0], [%1], 16;" :: "r"(dst), "l"(src) : "memory");
}
static __device__ __forceinline__ void ldsm4(uint32_t* r, uint32_t addr) {
    asm volatile("ldmatrix.sync.aligned.m8n8.x4.shared.b16 {%0,%1,%2,%3}, [%4];"
                 : "=r"(r[0]), "=r"(r[1]), "=r"(r[2]), "=r"(r[3]) : "r"(addr));
}
static __device__ __forceinline__ void mma16816(float* d, const uint32_t* a, uint32_t b0, uint32_t b1) {
    asm volatile("mma.sync.aligned.m16n8k16.row.col.f32.f16.f16.f32 "
                 "{%0,%1,%2,%3}, {%4,%5,%6,%7}, {%8,%9}, {%0,%1,%2,%3};"
                 : "+f"(d[0]), "+f"(d[1]), "+f"(d[2]), "+f"(d[3])
                 : "r"(a[0]), "r"(a[1]), "r"(a[2]), "r"(a[3]), "r"(b0), "r"(b1));
}

// ---------------- pack: fp32 -> fp16, grid-stride fat kernels ----------------
// V half: 8,388,608 quads; 512 CTAs x 256 thr x 64 iters. qoff selects half.
__global__ __launch_bounds__(256) void k_packV(const float* __restrict__ V, uint32_t qoff) {
    const uint32_t stride = 512 * 256;
    uint32_t idx = qoff + blockIdx.x * 256 + threadIdx.x;
    #pragma unroll 4
    for (int it = 0; it < 64; ++it, idx += stride) {
        float4 v = ((const float4*)V)[idx];
        __half2 h01 = __floats2half2_rn(v.x, v.y);
        __half2 h23 = __floats2half2_rn(v.z, v.w);
        ((uint2*)g_Vh)[idx] = make_uint2(*(uint32_t*)&h01, *(uint32_t*)&h23);
    }
}
__global__ __launch_bounds__(256) void k_packU(const float* __restrict__ U) {
    const uint32_t stride = 128 * 256;
    uint32_t idx = blockIdx.x * 256 + threadIdx.x;
    #pragma unroll 4
    for (int it = 0; it < 8; ++it, idx += stride) {
        float4 v = ((const float4*)U)[idx];
        __half2 h01 = __floats2half2_rn(v.x, v.y);
        __half2 h23 = __floats2half2_rn(v.z, v.w);
        ((uint2*)g_Uh)[idx] = make_uint2(*(uint32_t*)&h01, *(uint32_t*)&h23);
    }
}

// ---------------- main GEMM: R13 config (best known), + i-offset ----------------
// C[256x128] tile, 256 thr / 8 warps of 64x64. Per half: grid (64,4), i-fastest.
// smem per stage: A[256x128B]=32KB + B[128x128B]=16KB, xor-swizzled.
#define SMEM_BYTES (NSTAGE * STG + 512 + 4096 + 1024)

__global__ __launch_bounds__(256, 1) void k_scores_tc(const float* __restrict__ Wm, int ioff)
{
    extern __shared__ uint8_t dsm[];
    uint32_t raw = smem_u32(dsm);
    uint32_t sb  = (raw + 1023) & ~1023u;
    uint8_t* sp  = dsm + (sb - raw);
    float* Wsh   = (float*)(sp + NSTAGE * STG);
    float* part  = (float*)(sp + NSTAGE * STG + 512);   // [2][256]

    const int tid  = threadIdx.x;
    const int lane = tid & 31, wid = tid >> 5;          // 8 warps
    const int wm = wid & 3, wn = wid >> 2;              // warp tile: rows wm*64, cols wn*64
    const int ibase = (blockIdx.x + ioff) * TM;
    const int jbase = blockIdx.y * TN;

    if (tid < TN) Wsh[tid] = Wm[jbase + tid];

    const uint8_t* aT = g_Vh + (size_t)ibase * (D * 2);
    const uint8_t* bT = g_Uh + (size_t)jbase * (D * 2);

    // cp.async loader: 256 threads; A 8 chunks + B 4 chunks of 16B each
    const uint32_t lrow   = tid >> 3;                       // 0..31
    const uint32_t lc16   = (tid & 7) * 16;
    const uint32_t ld_dst = lc16 ^ ((lrow & 7) << 4);       // swizzled col part

    // ldmatrix constants
    const uint32_t mask  = (lane & 7) << 4;
    const uint32_t aRow  = (wm * 64 + (lane & 15)) * 128;
    const uint32_t bRow  = (wn * 64 + (lane & 7) + ((lane >> 1) & 8)) * 128;
    const uint32_t kselA = (lane & 16);        // k-half select for A x4
    const uint32_t kselB = (lane & 8) << 1;    // k-half select for B x4

    float acc[4][8][4];
    #pragma unroll
    for (int a = 0; a < 4; ++a)
        #pragma unroll
        for (int b = 0; b < 8; ++b)
            #pragma unroll
            for (int c = 0; c < 4; ++c) acc[a][b][c] = 0.f;

    auto load_stage = [&](int s) {
        const int buf = s & (NSTAGE - 1);
        const uint8_t* as = aT + (size_t)s * 128;
        const uint8_t* bs = bT + (size_t)s * 128;
        const uint32_t dA = sb + buf * STG;
        const uint32_t dB = dA + 32768;
        #pragma unroll
        for (int q = 0; q < 8; ++q) {
            uint32_t row = lrow + q * 32;
            cp16(dA + row * 128 + ld_dst, as + (size_t)row * 4096 + lc16);
        }
        #pragma unroll
        for (int q = 0; q < 4; ++q) {
            uint32_t row = lrow + q * 32;
            cp16(dB + row * 128 + ld_dst, bs + (size_t)row * 4096 + lc16);
        }
        asm volatile("cp.async.commit_group;" ::: "memory");
    };

    load_stage(0); load_stage(1); load_stage(2);

    #pragma unroll 1
    for (int s = 0; s < NSTOT; ++s) {
        asm volatile("cp.async.wait_group 2;" ::: "memory");
        __syncthreads();
        const int buf = s & (NSTAGE - 1);
        const uint32_t smA = sb + buf * STG;
        const uint32_t smB = smA + 32768;

        #pragma unroll
        for (int kk = 0; kk < 4; ++kk) {
            const uint32_t kxA = (kk * 32 + kselA) ^ mask;
            const uint32_t kxB = (kk * 32 + kselB) ^ mask;
            uint32_t Af[4][4], Bf[4][4];
            #pragma unroll
            for (int mt = 0; mt < 4; ++mt) ldsm4(Af[mt], smA + aRow + mt * 2048 + kxA);
            #pragma unroll
            for (int p = 0; p < 4; ++p)   ldsm4(Bf[p],  smB + bRow + p  * 2048 + kxB);
            #pragma unroll
            for (int mt = 0; mt < 4; ++mt)
                #pragma unroll
                for (int nt = 0; nt < 8; ++nt) {
                    const uint32_t* B = Bf[nt >> 1];
                    mma16816(acc[mt][nt], Af[mt],
                             (nt & 1) ? B[2] : B[0], (nt & 1) ? B[3] : B[1]);
                }
        }
        if (s + 3 < NSTOT) load_stage(s + 3);
    }

    // ---- epilogue: s_part[i] = sum_{j in tile} w_j * tanh(c_ij) ----
    const int gr = lane >> 2;
    const int gc = (lane & 3) * 2;
    #pragma unroll
    for (int mt = 0; mt < 4; ++mt) {
        float l0 = 0.f, l1 = 0.f;
        #pragma unroll
        for (int nt = 0; nt < 8; ++nt) {
            int wi = wn * 64 + nt * 8 + gc;
            float w0 = Wsh[wi], w1 = Wsh[wi + 1];
            l0 += w0 * tanhf(acc[mt][nt][0]) + w1 * tanhf(acc[mt][nt][1]);
            l1 += w0 * tanhf(acc[mt][nt][2]) + w1 * tanhf(acc[mt][nt][3]);
        }
        l0 += __shfl_xor_sync(0xffffffffu, l0, 1);
        l0 += __shfl_xor_sync(0xffffffffu, l0, 2);
        l1 += __shfl_xor_sync(0xffffffffu, l1, 1);
        l1 += __shfl_xor_sync(0xffffffffu, l1, 2);
        if ((lane & 3) == 0) {
            part[wn * 256 + wm * 64 + mt * 16 + gr]     = l0;
            part[wn * 256 + wm * 64 + mt * 16 + 8 + gr] = l1;
        }
    }
    __syncthreads();
    if (tid < 256) {
        float sv = part[tid] + part[256 + tid];
        g_Sp[blockIdx.y][ibase + tid] = sv;
    }
}

// ---------------- parallel softmax stats (2 tiny kernels) ----------------
__global__ __launch_bounds__(512) void k_smax1() {
    __shared__ float sm[512];
    const int tid = threadIdx.x;
    const int i = blockIdx.x * 512 + tid;
    float s = g_Sp[0][i] + g_Sp[1][i] + g_Sp[2][i] + g_Sp[3][i];
    g_S[i] = s;
    sm[tid] = s; __syncthreads();
    for (int o = 256; o > 0; o >>= 1) {
        if (tid < o) sm[tid] = fmaxf(sm[tid], sm[tid + o]);
        __syncthreads();
    }
    const float bm = sm[0];
    __syncthreads();
    sm[tid] = expf(s - bm); __syncthreads();
    for (int o = 256; o > 0; o >>= 1) {
        if (tid < o) sm[tid] += sm[tid + o];
        __syncthreads();
    }
    if (tid == 0) { g_bm[blockIdx.x] = bm; g_bz[blockIdx.x] = sm[0]; }
}
__global__ void k_smax2() {
    __shared__ float m[64], z[64];
    const int tid = threadIdx.x;   // 64
    m[tid] = g_bm[tid]; z[tid] = g_bz[tid];
    __syncthreads();
    for (int o = 32; o > 0; o >>= 1) {
        if (tid < o) m[tid] = fmaxf(m[tid], m[tid + o]);
        __syncthreads();
    }
    const float M = m[0];
    __syncthreads();
    z[tid] *= expf(g_bm[tid] - M);
    __syncthreads();
    for (int o = 32; o > 0; o >>= 1) {
        if (tid < o) z[tid] += z[tid + o];
        __syncthreads();
    }
    if (tid == 0) { g_MZ[0] = M; g_MZ[1] = 1.0f / z[0]; }
}

// ---------------- pooling: fp16 V, high-MLP, fused normalize ----------------
__global__ __launch_bounds__(256) void k_pool() {
    __shared__ float ash[256];
    const int tid = threadIdx.x;
    const int c   = blockIdx.x * 1024 + tid * 4;
    const int i0  = blockIdx.y * 256;
    const float M = g_MZ[0], invZ = g_MZ[1];

    ash[tid] = expf(g_S[i0 + tid] - M) * invZ;
    __syncthreads();

    float4 acc = make_float4(0.f, 0.f, 0.f, 0.f);
    const uint2* vp = (const uint2*)(g_Vh + ((size_t)i0 * D + c) * 2);
    #pragma unroll 8
    for (int i = 0; i < 256; ++i) {
        float a = ash[i];
        uint2 r = vp[(size_t)i * (D / 4)];
        float2 f0 = __half22float2(*(const __half2*)&r.x);
        float2 f1 = __half22float2(*(const __half2*)&r.y);
        acc.x += a * f0.x; acc.y += a * f0.y;
        acc.z += a * f1.x; acc.w += a * f1.y;
    }
    *(float4*)&g_tp[blockIdx.y][c] = acc;
}
__global__ void k_pool_reduce() {
    const int k = blockIdx.x * blockDim.x + threadIdx.x;
    float s = 0.f;
    #pragma unroll
    for (int r = 0; r < 128; ++r) s += g_tp[r][k];
    g_t[k] = s;
}

// ---------------- final linear ----------------
__global__ void k_final(const float* __restrict__ W, float* __restrict__ out) {
    const int c    = threadIdx.y;
    const int lane = threadIdx.x;
    float s = 0.f;
    for (int k = lane; k < D; k += 32) s += W[c * D + k] * g_t[k];
    #pragma unroll
    for (int o = 16; o > 0; o >>= 1) s += __shfl_down_sync(0xffffffff, s, o);
    if (lane == 0) out[c] = s;
}

// ---------------- launcher: fork; packV-half1 co-resides with GEMM-half0 ----------------
// (Viable now: GEMM CTA = 256 thr x ~180 regs ~= 46k regs, leaving room for a
//  256-thr packV CTA per SM — unlike R10's 512x128 full-RF tenant.)
extern "C" void kernel_launch(void* const* d_in, const int* in_sizes, int n_in,
                              void* d_out, int out_size)
{
    const float* V  = (const float*)d_in[0];   // V_prime [32768, 2048]
    const float* U  = (const float*)d_in[1];   // U_t     [512, 2048]
    const float* Wm = (const float*)d_in[2];   // W_mta   [1, 512]
    const float* W  = (const float*)d_in[3];   // W       [4, 2048]
    float* out = (float*)d_out;

    cudaFuncSetAttribute(k_scores_tc, cudaFuncAttributeMaxDynamicSharedMemorySize, SMEM_BYTES);

    cudaStream_t s0 = 0;
    cudaStream_t t;
    cudaStreamCreateWithFlags(&t, cudaStreamNonBlocking);
    cudaEvent_t e1, e2;
    cudaEventCreateWithFlags(&e1, cudaEventDisableTiming);
    cudaEventCreateWithFlags(&e2, cudaEventDisableTiming);

    // main stream: packU + V half 0
    k_packU<<<128, 256, 0, s0>>>(U);
    k_packV<<<512, 256, 0, s0>>>(V, 0);
    cudaEventRecord(e1, s0);

    // side stream: V half 1 (co-resident with GEMM half 0), then GEMM half 1
    cudaStreamWaitEvent(t, e1, 0);
    k_packV<<<512, 256, 0, t>>>(V, 8388608);
    k_scores_tc<<<dim3(64, 4), 256, SMEM_BYTES, t>>>(Wm, 64);
    cudaEventRecord(e2, t);

    // main stream: GEMM half 0 (concurrent)
    k_scores_tc<<<dim3(64, 4), 256, SMEM_BYTES, s0>>>(Wm, 0);

    // join, then the cheap tail
    cudaStreamWaitEvent(s0, e2, 0);
    k_smax1<<<64, 512, 0, s0>>>();
    k_smax2<<<1, 64, 0, s0>>>();
    k_pool<<<dim3(2, 128), 256, 0, s0>>>();
    k_pool_reduce<<<2, 1024, 0, s0>>>();
    k_final<<<1, dim3(32, 4), 0, s0>>>(W, out);
    // Stream/event handles intentionally not destroyed (capture-safe; no device mem).
}

// round 16
// speedup vs baseline: 1.1740x; 1.0094x over previous
#include <cuda_runtime.h>
#include <cuda_fp16.h>
#include <math.h>
#include <stdint.h>

#define N_INST 32768
#define D      2048
#define DP     512
#define CLASSES 4

#define TM 256            // instances per CTA
#define TN 128            // j per CTA
#define NSTAGE 4          // smem buffers (3 in flight)
#define STG 49152         // 32KB A + 16KB B per stage
#define NSTOT 32          // 32 k-tiles of 64

// ---------------- scratch (module-scope, no runtime allocation) ----------------
__device__ __align__(1024) uint8_t g_Vh[(size_t)N_INST * D * 2];   // fp16 V
__device__ __align__(1024) uint8_t g_Uh[DP * D * 2];               // fp16 U
__device__ float g_Sp[4][N_INST];   // per-j-tile logit partials
__device__ float g_S[N_INST];
__device__ float g_bm[64], g_bz[64];
__device__ float g_tp[128][D];
__device__ float g_t[D];

// ---------------- PTX helpers (plain sm_80-era features only) ----------------
static __device__ __forceinline__ uint32_t smem_u32(const void* p) {
    uint32_t a;
    asm("{ .reg .u64 t; cvta.to.shared.u64 t, %1; cvt.u32.u64 %0, t; }" : "=r"(a) : "l"(p));
    return a;
}
static __device__ __forceinline__ void cp16(uint32_t dst, const void* src) {
    asm volatile("cp.async.cg.shared.global [%0], [%1], 16;" :: "r"(dst), "l"(src) : "memory");
}
static __device__ __forceinline__ void ldsm4(uint32_t* r, uint32_t addr) {
    asm volatile("ldmatrix.sync.aligned.m8n8.x4.shared.b16 {%0,%1,%2,%3}, [%4];"
                 : "=r"(r[0]), "=r"(r[1]), "=r"(r[2]), "=r"(r[3]) : "r"(addr));
}
static __device__ __forceinline__ void mma16816(float* d, const uint32_t* a, uint32_t b0, uint32_t b1) {
    asm volatile("mma.sync.aligned.m16n8k16.row.col.f32.f16.f16.f32 "
                 "{%0,%1,%2,%3}, {%4,%5,%6,%7}, {%8,%9}, {%0,%1,%2,%3};"
                 : "+f"(d[0]), "+f"(d[1]), "+f"(d[2]), "+f"(d[3])
                 : "r"(a[0]), "r"(a[1]), "r"(a[2]), "r"(a[3]), "r"(b0), "r"(b1));
}

// ---------------- pack: fp32 -> fp16, grid-stride fat kernels ----------------
__global__ __launch_bounds__(256) void k_packV(const float* __restrict__ V, uint32_t qoff) {
    const uint32_t stride = 512 * 256;
    uint32_t idx = qoff + blockIdx.x * 256 + threadIdx.x;
    #pragma unroll 4
    for (int it = 0; it < 64; ++it, idx += stride) {
        float4 v = ((const float4*)V)[idx];
        __half2 h01 = __floats2half2_rn(v.x, v.y);
        __half2 h23 = __floats2half2_rn(v.z, v.w);
        ((uint2*)g_Vh)[idx] = make_uint2(*(uint32_t*)&h01, *(uint32_t*)&h23);
    }
}
__global__ __launch_bounds__(256) void k_packU(const float* __restrict__ U) {
    const uint32_t stride = 128 * 256;
    uint32_t idx = blockIdx.x * 256 + threadIdx.x;
    #pragma unroll 4
    for (int it = 0; it < 8; ++it, idx += stride) {
        float4 v = ((const float4*)U)[idx];
        __half2 h01 = __floats2half2_rn(v.x, v.y);
        __half2 h23 = __floats2half2_rn(v.z, v.w);
        ((uint2*)g_Uh)[idx] = make_uint2(*(uint32_t*)&h01, *(uint32_t*)&h23);
    }
}

// ---------------- main GEMM: R13 config + reg cap for co-residency ----------------
// C[256x128] tile, 256 thr / 8 warps of 64x64. __maxnreg__(232) leaves 6144 regs
// free per SM so a 256-thread packV CTA can co-reside during the forked overlap.
// (Occupancy is already pinned to 1 CTA/SM by the 202KB smem footprint, so no
//  __launch_bounds__ needed — the two qualifiers can't be combined.)
#define SMEM_BYTES (NSTAGE * STG + 512 + 4096 + 1024)

__global__ void __maxnreg__(232)
k_scores_tc(const float* __restrict__ Wm, int ioff)
{
    extern __shared__ uint8_t dsm[];
    uint32_t raw = smem_u32(dsm);
    uint32_t sb  = (raw + 1023) & ~1023u;
    uint8_t* sp  = dsm + (sb - raw);
    float* Wsh   = (float*)(sp + NSTAGE * STG);
    float* part  = (float*)(sp + NSTAGE * STG + 512);   // [2][256]

    const int tid  = threadIdx.x;
    const int lane = tid & 31, wid = tid >> 5;          // 8 warps
    const int wm = wid & 3, wn = wid >> 2;              // warp tile: rows wm*64, cols wn*64
    const int ibase = (blockIdx.x + ioff) * TM;
    const int jbase = blockIdx.y * TN;

    if (tid < TN) Wsh[tid] = Wm[jbase + tid];

    const uint8_t* aT = g_Vh + (size_t)ibase * (D * 2);
    const uint8_t* bT = g_Uh + (size_t)jbase * (D * 2);

    const uint32_t lrow   = tid >> 3;                       // 0..31
    const uint32_t lc16   = (tid & 7) * 16;
    const uint32_t ld_dst = lc16 ^ ((lrow & 7) << 4);       // swizzled col part

    const uint32_t mask  = (lane & 7) << 4;
    const uint32_t aRow  = (wm * 64 + (lane & 15)) * 128;
    const uint32_t bRow  = (wn * 64 + (lane & 7) + ((lane >> 1) & 8)) * 128;
    const uint32_t kselA = (lane & 16);
    const uint32_t kselB = (lane & 8) << 1;

    float acc[4][8][4];
    #pragma unroll
    for (int a = 0; a < 4; ++a)
        #pragma unroll
        for (int b = 0; b < 8; ++b)
            #pragma unroll
            for (int c = 0; c < 4; ++c) acc[a][b][c] = 0.f;

    auto load_stage = [&](int s) {
        const int buf = s & (NSTAGE - 1);
        const uint8_t* as = aT + (size_t)s * 128;
        const uint8_t* bs = bT + (size_t)s * 128;
        const uint32_t dA = sb + buf * STG;
        const uint32_t dB = dA + 32768;
        #pragma unroll
        for (int q = 0; q < 8; ++q) {
            uint32_t row = lrow + q * 32;
            cp16(dA + row * 128 + ld_dst, as + (size_t)row * 4096 + lc16);
        }
        #pragma unroll
        for (int q = 0; q < 4; ++q) {
            uint32_t row = lrow + q * 32;
            cp16(dB + row * 128 + ld_dst, bs + (size_t)row * 4096 + lc16);
        }
        asm volatile("cp.async.commit_group;" ::: "memory");
    };

    load_stage(0); load_stage(1); load_stage(2);

    #pragma unroll 1
    for (int s = 0; s < NSTOT; ++s) {
        asm volatile("cp.async.wait_group 2;" ::: "memory");
        __syncthreads();
        const int buf = s & (NSTAGE - 1);
        const uint32_t smA = sb + buf * STG;
        const uint32_t smB = smA + 32768;

        #pragma unroll
        for (int kk = 0; kk < 4; ++kk) {
            const uint32_t kxA = (kk * 32 + kselA) ^ mask;
            const uint32_t kxB = (kk * 32 + kselB) ^ mask;
            uint32_t Af[4][4], Bf[4][4];
            #pragma unroll
            for (int mt = 0; mt < 4; ++mt) ldsm4(Af[mt], smA + aRow + mt * 2048 + kxA);
            #pragma unroll
            for (int p = 0; p < 4; ++p)   ldsm4(Bf[p],  smB + bRow + p  * 2048 + kxB);
            #pragma unroll
            for (int mt = 0; mt < 4; ++mt)
                #pragma unroll
                for (int nt = 0; nt < 8; ++nt) {
                    const uint32_t* B = Bf[nt >> 1];
                    mma16816(acc[mt][nt], Af[mt],
                             (nt & 1) ? B[2] : B[0], (nt & 1) ? B[3] : B[1]);
                }
        }
        if (s + 3 < NSTOT) load_stage(s + 3);
    }

    // ---- epilogue: s_part[i] = sum_{j in tile} w_j * tanh(c_ij) ----
    const int gr = lane >> 2;
    const int gc = (lane & 3) * 2;
    #pragma unroll
    for (int mt = 0; mt < 4; ++mt) {
        float l0 = 0.f, l1 = 0.f;
        #pragma unroll
        for (int nt = 0; nt < 8; ++nt) {
            int wi = wn * 64 + nt * 8 + gc;
            float w0 = Wsh[wi], w1 = Wsh[wi + 1];
            l0 += w0 * tanhf(acc[mt][nt][0]) + w1 * tanhf(acc[mt][nt][1]);
            l1 += w0 * tanhf(acc[mt][nt][2]) + w1 * tanhf(acc[mt][nt][3]);
        }
        l0 += __shfl_xor_sync(0xffffffffu, l0, 1);
        l0 += __shfl_xor_sync(0xffffffffu, l0, 2);
        l1 += __shfl_xor_sync(0xffffffffu, l1, 1);
        l1 += __shfl_xor_sync(0xffffffffu, l1, 2);
        if ((lane & 3) == 0) {
            part[wn * 256 + wm * 64 + mt * 16 + gr]     = l0;
            part[wn * 256 + wm * 64 + mt * 16 + 8 + gr] = l1;
        }
    }
    __syncthreads();
    if (tid < 256) {
        float sv = part[tid] + part[256 + tid];
        g_Sp[blockIdx.y][ibase + tid] = sv;
    }
}

// ---------------- softmax stage 1: per-512-block max & partial Z ----------------
__global__ __launch_bounds__(512) void k_smax1() {
    __shared__ float sm[512];
    const int tid = threadIdx.x;
    const int i = blockIdx.x * 512 + tid;
    float s = g_Sp[0][i] + g_Sp[1][i] + g_Sp[2][i] + g_Sp[3][i];
    g_S[i] = s;
    sm[tid] = s; __syncthreads();
    for (int o = 256; o > 0; o >>= 1) {
        if (tid < o) sm[tid] = fmaxf(sm[tid], sm[tid + o]);
        __syncthreads();
    }
    const float bm = sm[0];
    __syncthreads();
    sm[tid] = expf(s - bm); __syncthreads();
    for (int o = 256; o > 0; o >>= 1) {
        if (tid < o) sm[tid] += sm[tid + o];
        __syncthreads();
    }
    if (tid == 0) { g_bm[blockIdx.x] = bm; g_bz[blockIdx.x] = sm[0]; }
}

// ---------------- pooling: fp16 V, fused global softmax finalize + normalize ----------------
// grid (2,128); each CTA re-derives M,invZ from the 64 block stats (cheap, redundant).
__global__ __launch_bounds__(256) void k_pool() {
    __shared__ float ash[256];
    __shared__ float sMZ[2];
    const int tid = threadIdx.x;
    const int c   = blockIdx.x * 1024 + tid * 4;
    const int i0  = blockIdx.y * 256;

    if (tid < 32) {
        float m = fmaxf(g_bm[tid], g_bm[tid + 32]);
        #pragma unroll
        for (int o = 16; o > 0; o >>= 1) m = fmaxf(m, __shfl_xor_sync(0xffffffffu, m, o));
        if (tid == 0) sMZ[0] = m;
    }
    __syncthreads();
    if (tid < 32) {
        float M = sMZ[0];
        float z = g_bz[tid] * expf(g_bm[tid] - M) + g_bz[tid + 32] * expf(g_bm[tid + 32] - M);
        #pragma unroll
        for (int o = 16; o > 0; o >>= 1) z += __shfl_xor_sync(0xffffffffu, z, o);
        if (tid == 0) sMZ[1] = 1.0f / z;
    }
    __syncthreads();
    const float M = sMZ[0], invZ = sMZ[1];

    ash[tid] = expf(g_S[i0 + tid] - M) * invZ;
    __syncthreads();

    float4 acc = make_float4(0.f, 0.f, 0.f, 0.f);
    const uint2* vp = (const uint2*)(g_Vh + ((size_t)i0 * D + c) * 2);
    #pragma unroll 8
    for (int i = 0; i < 256; ++i) {
        float a = ash[i];
        uint2 r = vp[(size_t)i * (D / 4)];
        float2 f0 = __half22float2(*(const __half2*)&r.x);
        float2 f1 = __half22float2(*(const __half2*)&r.y);
        acc.x += a * f0.x; acc.y += a * f0.y;
        acc.z += a * f1.x; acc.w += a * f1.y;
    }
    *(float4*)&g_tp[blockIdx.y][c] = acc;
}
__global__ void k_pool_reduce() {
    const int k = blockIdx.x * blockDim.x + threadIdx.x;
    float s = 0.f;
    #pragma unroll
    for (int r = 0; r < 128; ++r) s += g_tp[r][k];
    g_t[k] = s;
}

// ---------------- final linear ----------------
__global__ void k_final(const float* __restrict__ W, float* __restrict__ out) {
    const int c    = threadIdx.y;
    const int lane = threadIdx.x;
    float s = 0.f;
    for (int k = lane; k < D; k += 32) s += W[c * D + k] * g_t[k];
    #pragma unroll
    for (int o = 16; o > 0; o >>= 1) s += __shfl_down_sync(0xffffffff, s, o);
    if (lane == 0) out[c] = s;
}

// ---------------- launcher: fork; packV-half1 co-resides with GEMM-half0 ----------------
extern "C" void kernel_launch(void* const* d_in, const int* in_sizes, int n_in,
                              void* d_out, int out_size)
{
    const float* V  = (const float*)d_in[0];   // V_prime [32768, 2048]
    const float* U  = (const float*)d_in[1];   // U_t     [512, 2048]
    const float* Wm = (const float*)d_in[2];   // W_mta   [1, 512]
    const float* W  = (const float*)d_in[3];   // W       [4, 2048]
    float* out = (float*)d_out;

    cudaFuncSetAttribute(k_scores_tc, cudaFuncAttributeMaxDynamicSharedMemorySize, SMEM_BYTES);

    cudaStream_t s0 = 0;
    cudaStream_t t;
    cudaStreamCreateWithFlags(&t, cudaStreamNonBlocking);
    cudaEvent_t e1, e2;
    cudaEventCreateWithFlags(&e1, cudaEventDisableTiming);
    cudaEventCreateWithFlags(&e2, cudaEventDisableTiming);

    // main stream: packU + V half 0
    k_packU<<<128, 256, 0, s0>>>(U);
    k_packV<<<512, 256, 0, s0>>>(V, 0);
    cudaEventRecord(e1, s0);

    // side stream: V half 1 (co-resident with GEMM half 0), then GEMM half 1
    cudaStreamWaitEvent(t, e1, 0);
    k_packV<<<512, 256, 0, t>>>(V, 8388608);
    k_scores_tc<<<dim3(64, 4), 256, SMEM_BYTES, t>>>(Wm, 64);
    cudaEventRecord(e2, t);

    // main stream: GEMM half 0 (concurrent)
    k_scores_tc<<<dim3(64, 4), 256, SMEM_BYTES, s0>>>(Wm, 0);

    // join, then the cheap tail
    cudaStreamWaitEvent(s0, e2, 0);
    k_smax1<<<64, 512, 0, s0>>>();
    k_pool<<<dim3(2, 128), 256, 0, s0>>>();
    k_pool_reduce<<<2, 1024, 0, s0>>>();
    k_final<<<1, dim3(32, 4), 0, s0>>>(W, out);
    // Stream/event handles intentionally not destroyed (capture-safe; no device mem).
}